// round 8
// baseline (speedup 1.0000x reference)
#include <cuda_runtime.h>
#include <math.h>

#define B_   256
#define T_   128
#define I_   512
#define H_   512
#define NN   1024
#define MM   512
#define OO   512
#define PW_  518          // M+6
#define PSTR 520
#define EPS  1e-8f
#define NB   144
#define NT   512

// ---------------- persistent device state ----------------
__device__ __align__(256) float g_mem[NN * MM];
__device__ __align__(256) float g_wr[B_ * NN];
__device__ __align__(256) float g_ww[B_ * NN];
__device__ __align__(256) float g_EA[B_ * 2 * MM];    // pre-act EA accum (seed bea)
__device__ __align__(256) float g_r[B_ * MM];         // r accum (seed 0)
__device__ __align__(256) float g_hpre[B_ * H_];      // h pre-act accum (seed bh)
__device__ __align__(256) float g_Pw[B_ * PSTR];      // head pre-act (seed bias)
__device__ __align__(256) float g_Pr[B_ * PSTR];
__device__ __align__(256) float g_Cw[B_ * NN];        // scores accum (seed 0)
__device__ __align__(256) float g_Cr[B_ * NN];
__device__ __align__(256) float g_opre[B_ * OO];      // out pre-act (seed bo)
__device__ __align__(256) float g_memnorm[NN];
__device__ unsigned g_cnt;
__device__ volatile unsigned g_sense;

// ---------------- scalar helpers ----------------
__device__ __forceinline__ float sigmoidf_(float x) { return 1.f / (1.f + expf(-x)); }
__device__ __forceinline__ float softplusf_(float x) {
    return fmaxf(x, 0.f) + log1pf(expf(-fabsf(x)));
}
__device__ __forceinline__ float warpSum(float v) {
    #pragma unroll
    for (int o = 16; o; o >>= 1) v += __shfl_xor_sync(0xffffffffu, v, o);
    return v;
}
__device__ __forceinline__ float warpMax(float v) {
    #pragma unroll
    for (int o = 16; o; o >>= 1) v = fmaxf(v, __shfl_xor_sync(0xffffffffu, v, o));
    return v;
}

// ---------------- packed f32x2 helpers (Blackwell FFMA2) ----------------
__device__ __forceinline__ unsigned long long pack2(float a, float b) {
    unsigned long long r;
    asm("mov.b64 %0, {%1, %2};" : "=l"(r) : "f"(a), "f"(b));
    return r;
}
__device__ __forceinline__ void fma2(unsigned long long& d,
                                     unsigned long long a, unsigned long long b) {
    asm("fma.rn.f32x2 %0, %1, %2, %0;" : "+l"(d) : "l"(a), "l"(b));
}
__device__ __forceinline__ float2 unpack2(unsigned long long v) {
    float2 r;
    asm("mov.b64 {%0, %1}, %2;" : "=f"(r.x), "=f"(r.y) : "l"(v));
    return r;
}

// ---------------- grid barrier ----------------
__device__ __forceinline__ void gbar(unsigned& sense) {
    __threadfence();
    __syncthreads();
    if (threadIdx.x == 0) {
        unsigned ns = sense ^ 1u;
        if (atomicAdd(&g_cnt, 1u) == NB - 1u) {
            atomicExch(&g_cnt, 0u);
            __threadfence();
            g_sense = ns;
        } else {
            while (g_sense != ns) __nanosleep(32);
        }
        sense = ns;
        __threadfence();
    }
    __syncthreads();
}

// ---------------- 256-thread group barrier / reductions ----------------
__device__ __forceinline__ void barx(int id) {
    asm volatile("bar.sync %0, 256;" :: "r"(id) : "memory");
}
__device__ float grpSum(float v, float* red, int id) {
    int t = threadIdx.x & 255;
    int lane = t & 31, w = t >> 5;
    v = warpSum(v);
    if (lane == 0) red[w] = v;
    barx(id);
    float s = 0.f;
    #pragma unroll
    for (int i = 0; i < 8; i++) s += red[i];
    barx(id);
    return s;
}
__device__ float grpMax(float v, float* red, int id) {
    int t = threadIdx.x & 255;
    int lane = t & 31, w = t >> 5;
    v = warpMax(v);
    if (lane == 0) red[w] = v;
    barx(id);
    float m = red[0];
    #pragma unroll
    for (int i = 1; i < 8; i++) m = fmaxf(m, red[i]);
    barx(id);
    return m;
}

// ---------------- 128x64 GEMM tile, packed acc 4x(2x2), double-buffered ----
// BMODE 0: W row-major full tile; 1: row-major + col guard; 2: transposed src.
// EPI 1: atomicAdd into C. ATANH: tanh on A elements.
template<bool ATANH, int BMODE, int EPI>
__device__ void tile_gemm2(
    float* sh,
    const float* __restrict__ A, int lda,
    const float* __restrict__ W, int wld, int wvalid,
    float* __restrict__ C, int ldc, int K)
{
    float* As = sh;          // [2][16*132]
    float* Bs = sh + 4224;   // [2][16*68]
    const int tid = threadIdx.x;
    const int aR = tid >> 2, aK = (tid & 3) * 4;
    const int bK = tid >> 5, bC = (tid & 31) * 2;
    const int b2n = tid & 63, b2k = (tid >> 6) * 2;
    const int ty = tid >> 4, tx = tid & 15;
    float ar[4], bw[2];

    auto loadA = [&](int k0) {
        float4 v = *(const float4*)(A + (size_t)aR * lda + k0 + aK);
        if (ATANH) {
            v.x = tanhf(v.x); v.y = tanhf(v.y);
            v.z = tanhf(v.z); v.w = tanhf(v.w);
        }
        ar[0] = v.x; ar[1] = v.y; ar[2] = v.z; ar[3] = v.w;
    };
    auto loadB = [&](int k0) {
        if (BMODE == 0) {
            float2 v = *(const float2*)(W + (size_t)(k0 + bK) * wld + bC);
            bw[0] = v.x; bw[1] = v.y;
        } else if (BMODE == 1) {
            bw[0] = (bC     < wvalid) ? W[(size_t)(k0 + bK) * wld + bC]     : 0.f;
            bw[1] = (bC + 1 < wvalid) ? W[(size_t)(k0 + bK) * wld + bC + 1] : 0.f;
        } else {
            float2 v = *(const float2*)(W + (size_t)b2n * wld + k0 + b2k);
            bw[0] = v.x; bw[1] = v.y;
        }
    };
    auto storeAB = [&](int buf) {
        float* Ab = As + buf * 2112;
        #pragma unroll
        for (int u = 0; u < 4; u++) Ab[(aK + u) * 132 + aR] = ar[u];
        float* Bb = Bs + buf * 1088;
        if (BMODE == 2) {
            Bb[b2k * 68 + b2n] = bw[0];
            Bb[(b2k + 1) * 68 + b2n] = bw[1];
        } else {
            *(float2*)&Bb[bK * 68 + bC] = make_float2(bw[0], bw[1]);
        }
    };

    unsigned long long acc2[4][2] = {};
    loadA(0); loadB(0); storeAB(0);
    __syncthreads();
    int buf = 0;
    for (int k0 = 0; k0 < K; k0 += 16) {
        bool more = (k0 + 16) < K;
        if (more) { loadA(k0 + 16); loadB(k0 + 16); }
        float* Ab = As + buf * 2112;
        float* Bb = Bs + buf * 1088;
        #pragma unroll
        for (int kk = 0; kk < 16; kk++) {
            float4 a4 = *(const float4*)&Ab[kk * 132 + ty * 4];
            ulonglong2 bp = *(const ulonglong2*)&Bb[kk * 68 + tx * 4];
            unsigned long long av;
            av = pack2(a4.x, a4.x); fma2(acc2[0][0], av, bp.x); fma2(acc2[0][1], av, bp.y);
            av = pack2(a4.y, a4.y); fma2(acc2[1][0], av, bp.x); fma2(acc2[1][1], av, bp.y);
            av = pack2(a4.z, a4.z); fma2(acc2[2][0], av, bp.x); fma2(acc2[2][1], av, bp.y);
            av = pack2(a4.w, a4.w); fma2(acc2[3][0], av, bp.x); fma2(acc2[3][1], av, bp.y);
        }
        if (more) storeAB(buf ^ 1);
        __syncthreads();
        buf ^= 1;
    }
    #pragma unroll
    for (int i = 0; i < 4; i++) {
        #pragma unroll
        for (int jp = 0; jp < 2; jp++) {
            float2 v = unpack2(acc2[i][jp]);
            int c0 = tx * 4 + jp * 2;
            float* rowp = C + (size_t)(ty * 4 + i) * ldc;
            if (BMODE != 1 || c0 < wvalid) {
                if (EPI == 1) atomicAdd(rowp + c0, v.x); else rowp[c0] = v.x;
            }
            if (BMODE != 1 || c0 + 1 < wvalid) {
                if (EPI == 1) atomicAdd(rowp + c0 + 1, v.y); else rowp[c0 + 1] = v.y;
            }
        }
    }
}

// ---------------- memory update tile 64n x 64m (dual packed acc, K=256) ----
__device__ void tile_memupd(float* sh, int n0, int m0)
{
    float* Ws  = sh;            // [2][32][68]
    float* Es  = sh + 4352;
    float* Aas = sh + 8704;
    const int tid = threadIdx.x;
    const int wK = tid >> 4, wC = (tid & 15) * 4;
    const int ty = tid >> 5, tx = tid & 31;
    float wr_[4], ev[4], av[4];

    auto loadAll = [&](int b0) {
        float4 w = *(const float4*)(g_ww + (size_t)(b0 + wK) * NN + n0 + wC);
        wr_[0] = w.x; wr_[1] = w.y; wr_[2] = w.z; wr_[3] = w.w;
        size_t ro = (size_t)(b0 + wK) * (2 * MM);
        float4 e0 = *(const float4*)(g_EA + ro + m0 + wC);
        float4 a0 = *(const float4*)(g_EA + ro + MM + m0 + wC);
        ev[0] = sigmoidf_(e0.x); ev[1] = sigmoidf_(e0.y);
        ev[2] = sigmoidf_(e0.z); ev[3] = sigmoidf_(e0.w);
        av[0] = tanhf(a0.x); av[1] = tanhf(a0.y);
        av[2] = tanhf(a0.z); av[3] = tanhf(a0.w);
    };
    auto storeAll = [&](int buf) {
        *(float4*)&Ws [buf * 2176 + wK * 68 + wC] = make_float4(wr_[0], wr_[1], wr_[2], wr_[3]);
        *(float4*)&Es [buf * 2176 + wK * 68 + wC] = make_float4(ev[0], ev[1], ev[2], ev[3]);
        *(float4*)&Aas[buf * 2176 + wK * 68 + wC] = make_float4(av[0], av[1], av[2], av[3]);
    };

    unsigned long long ae2[4] = {}, aa2[4] = {};
    loadAll(0); storeAll(0);
    __syncthreads();
    int buf = 0;
    for (int b0 = 0; b0 < B_; b0 += 32) {
        bool more = (b0 + 32) < B_;
        if (more) loadAll(b0 + 32);
        float* Wb = Ws + buf * 2176;
        float* Eb = Es + buf * 2176;
        float* Ab = Aas + buf * 2176;
        #pragma unroll
        for (int kk = 0; kk < 32; kk++) {
            float4 w4 = *(const float4*)&Wb[kk * 68 + ty * 4];
            unsigned long long e2 = *(const unsigned long long*)&Eb[kk * 68 + tx * 2];
            unsigned long long a2 = *(const unsigned long long*)&Ab[kk * 68 + tx * 2];
            unsigned long long wv;
            wv = pack2(w4.x, w4.x); fma2(ae2[0], wv, e2); fma2(aa2[0], wv, a2);
            wv = pack2(w4.y, w4.y); fma2(ae2[1], wv, e2); fma2(aa2[1], wv, a2);
            wv = pack2(w4.z, w4.z); fma2(ae2[2], wv, e2); fma2(aa2[2], wv, a2);
            wv = pack2(w4.w, w4.w); fma2(ae2[3], wv, e2); fma2(aa2[3], wv, a2);
        }
        if (more) storeAll(buf ^ 1);
        __syncthreads();
        buf ^= 1;
    }
    const float invB = 1.f / (float)B_;
    #pragma unroll
    for (int i = 0; i < 4; i++) {
        float2 e = unpack2(ae2[i]);
        float2 a = unpack2(aa2[i]);
        size_t idx = (size_t)(n0 + ty * 4 + i) * MM + m0 + tx * 2;
        float m0v = g_mem[idx], m1v = g_mem[idx + 1];
        g_mem[idx]     = m0v * (1.f - e.x * invB) + a.x * invB;
        g_mem[idx + 1] = m1v * (1.f - e.y * invB) + a.y * invB;
    }
}

// ---------------- per-row memory norms (64 rows per job) ----------------
__device__ void norm_job(int nj) {
    const int t = threadIdx.x;
    const int row = nj * 64 + (t >> 3);
    const int p = t & 7;
    const float* rp = g_mem + (size_t)row * MM;
    float s = 0.f;
    #pragma unroll
    for (int u = 0; u < 64; u++) {
        float v = rp[p + u * 8];
        s += v * v;
    }
    s += __shfl_xor_sync(0xffffffffu, s, 1);
    s += __shfl_xor_sync(0xffffffffu, s, 2);
    s += __shfl_xor_sync(0xffffffffu, s, 4);
    if (p == 0) g_memnorm[row] = sqrtf(s);
}

// ---------------- addressing: 2 jobs/block via 256-thread groups ----------
__device__ void addr_dual(float* sh, int idx) {
    const int g = threadIdx.x >> 8;          // group 0/1
    const int t = threadIdx.x & 255;
    const int id = 1 + g;                    // named barrier id
    float* swg  = sh + g * 1024;
    float* red  = sh + 2048 + g * 16;
    float* scal = sh + 2080 + g * 8;
    const int b = idx & 255, z = idx >> 8;
    const float* P = (z ? g_Pr : g_Pw) + (size_t)b * PSTR;
    const float* C = (z ? g_Cr : g_Cw) + (size_t)b * NN;
    float* wrow = (z ? g_wr : g_ww) + (size_t)b * NN;

    barx(id);                                // protect smem from previous job
    float k0 = tanhf(P[t]), k1 = tanhf(P[t + 256]);
    float s = grpSum(k0 * k0 + k1 * k1, red, id);
    if (t == 0) {
        scal[6] = sqrtf(s) + EPS;
        float p0 = P[MM], p1 = P[MM + 1], p2 = P[MM + 2];
        float p3 = P[MM + 3], p4 = P[MM + 4], p5 = P[MM + 5];
        scal[0] = softplusf_(p0);
        scal[1] = sigmoidf_(p1);
        float m = fmaxf(p2, fmaxf(p3, p4));
        float e0 = expf(p2 - m), e1 = expf(p3 - m), e2 = expf(p4 - m);
        float ss = e0 + e1 + e2;
        scal[2] = e0 / ss; scal[3] = e1 / ss; scal[4] = e2 / ss;
        scal[5] = 1.f + softplusf_(p5);
    }
    barx(id);
    float beta = scal[0], gg = scal[1], s0 = scal[2], s1 = scal[3], s2 = scal[4];
    float gamma = scal[5], knorm = scal[6];

    float v[4];
    float mx = -3.4e38f;
    #pragma unroll
    for (int u = 0; u < 4; u++) {
        int n = t + u * 256;
        float sc = beta * C[n] / (knorm * (g_memnorm[n] + EPS));
        v[u] = sc;
        mx = fmaxf(mx, sc);
    }
    mx = grpMax(mx, red, id);
    float se = 0.f;
    #pragma unroll
    for (int u = 0; u < 4; u++) {
        v[u] = expf(v[u] - mx);
        se += v[u];
    }
    se = grpSum(se, red, id);
    float inv = 1.f / se;
    #pragma unroll
    for (int u = 0; u < 4; u++) {
        int n = t + u * 256;
        swg[n] = gg * v[u] * inv + (1.f - gg) * wrow[n];
    }
    barx(id);
    float S = 0.f;
    #pragma unroll
    for (int u = 0; u < 4; u++) {
        int n = t + u * 256;
        float wt = s1 * swg[n] + s0 * swg[(n + 1) & (NN - 1)] + s2 * swg[(n - 1) & (NN - 1)];
        v[u] = powf(wt, gamma);
        S += v[u];
    }
    S = grpSum(S, red, id);
    float invS = 1.f / (S + EPS);
    #pragma unroll
    for (int u = 0; u < 4; u++)
        wrow[t + u * 256] = v[u] * invS;
}

// ---------------- seed helpers ----------------
__device__ void seed_bcast(float* dst, const float* src, int width, int total,
                           int part, int parts) {
    int per = total / parts;
    int base = part * per;
    for (int i = threadIdx.x; i < per; i += NT) {
        int idx = base + i;
        dst[idx] = src[idx % width];
    }
}
__device__ void seed_zero(float* dst, int total, int part, int parts) {
    int per4 = total / (4 * parts);
    float4* d = (float4*)dst + part * per4;
    float4 z = make_float4(0.f, 0.f, 0.f, 0.f);
    for (int i = threadIdx.x; i < per4; i += NT) d[i] = z;
}
__device__ void seed_pbias(float* dst, const float* bias, int part, int parts) {
    int per = B_ * PSTR / parts;
    int base = part * per;
    for (int i = threadIdx.x; i < per; i += NT) {
        int idx = base + i;
        int c = idx % PSTR;
        dst[idx] = (c < PW_) ? bias[c] : 0.f;
    }
}

// ---------------- the megakernel ----------------
__global__ void __launch_bounds__(NT, 1) ntm_mega(
    const float* __restrict__ x,
    const float* __restrict__ mem0, const float* __restrict__ wr0,
    const float* __restrict__ ww0, const float* __restrict__ h0,
    const float* __restrict__ Wx, const float* __restrict__ Wr,
    const float* __restrict__ bh,
    const float* __restrict__ Whr, const float* __restrict__ bhr,
    const float* __restrict__ Whw, const float* __restrict__ bhw,
    const float* __restrict__ Wea, const float* __restrict__ bea,
    const float* __restrict__ Wo, const float* __restrict__ bo,
    float* __restrict__ out)
{
    __shared__ __align__(16) float sh[13120];
    unsigned sense = 0;
    const int bid = blockIdx.x;
    const int tid = threadIdx.x;
    const int gthread = bid * NT + tid;

    // INIT-A: copy state; seed EA with bea
    for (int i = gthread; i < NN * MM; i += NB * NT) g_mem[i] = mem0[i];
    for (int i = gthread; i < B_ * NN; i += NB * NT) {
        g_wr[i] = wr0[i];
        g_ww[i] = ww0[i];
    }
    for (int j = bid; j < 4; j += NB)
        seed_bcast(g_EA, bea, 2 * MM, B_ * 2 * MM, j, 4);
    gbar(sense);                                             // 1

    // INIT-B: EA(0) += h0 @ Wea   (ksplit4, K=128, 128 jobs)
    for (int j = bid; j < 128; j += NB) {
        int ks = j & 3, rest = j >> 2;
        int row0 = (rest & 1) * 128, col0 = (rest >> 1) * 64;
        tile_gemm2<false, 0, 1>(sh,
            h0 + (size_t)row0 * H_ + ks * 128, H_,
            Wea + (size_t)(ks * 128) * (2 * MM) + col0, 2 * MM, 64,
            g_EA + (size_t)row0 * (2 * MM) + col0, 2 * MM, 128);
    }
    gbar(sense);                                             // 2

    for (int t = 0; t < T_; t++) {
        // ---- P1: memupd(128) + seeds(8) = 136 ----
        for (int j = bid; j < 136; j += NB) {
            if (j < 128) {
                tile_memupd(sh, (j >> 3) * 64, (j & 7) * 64);
            } else if (j < 130) {
                seed_zero(g_r, B_ * MM, j - 128, 2);
            } else if (j < 132) {
                seed_bcast(g_hpre, bh, H_, B_ * H_, j - 130, 2);
            } else if (j < 134) {
                seed_pbias(g_Pw, bhw, j - 132, 2);
            } else {
                seed_pbias(g_Pr, bhr, j - 134, 2);
            }
        }
        gbar(sense);

        // ---- P2: r(64, K=256) + hx(32, K=256) + norms(16) + seedC(8) = 120 --
        for (int j = bid; j < 120; j += NB) {
            if (j < 64) {
                int ks = j & 3, rest = j >> 2;
                int row0 = (rest & 1) * 128, col0 = (rest >> 1) * 64;
                tile_gemm2<false, 0, 1>(sh,
                    g_wr + (size_t)row0 * NN + ks * 256, NN,
                    g_mem + (size_t)(ks * 256) * MM + col0, MM, 64,
                    g_r + (size_t)row0 * MM + col0, MM, 256);
            } else if (j < 96) {
                int jj = j - 64;
                int ks = jj & 1, rest = jj >> 1;
                int row0 = (rest & 1) * 128, col0 = (rest >> 1) * 64;
                tile_gemm2<false, 0, 1>(sh,
                    x + (size_t)row0 * (T_ * I_) + (size_t)t * I_ + ks * 256, T_ * I_,
                    Wx + (size_t)(ks * 256) * H_ + col0, H_, 64,
                    g_hpre + (size_t)row0 * H_ + col0, H_, 256);
            } else if (j < 112) {
                norm_job(j - 96);
            } else {
                int jj = j - 112;
                if (jj < 4) seed_zero(g_Cw, B_ * NN, jj, 4);
                else        seed_zero(g_Cr, B_ * NN, jj - 4, 4);
            }
        }
        gbar(sense);

        // ---- P3: hr(128, K=64 ksplit8) + seedEA(4) + seedOpre(2) = 134 ----
        for (int j = bid; j < 134; j += NB) {
            if (j < 128) {
                int ks = j & 7, rest = j >> 3;
                int row0 = (rest & 1) * 128, col0 = (rest >> 1) * 64;
                tile_gemm2<false, 0, 1>(sh,
                    g_r + (size_t)row0 * MM + ks * 64, MM,
                    Wr + (size_t)(ks * 64) * H_ + col0, H_, 64,
                    g_hpre + (size_t)row0 * H_ + col0, H_, 64);
            } else if (j < 132) {
                seed_bcast(g_EA, bea, 2 * MM, B_ * 2 * MM, j - 128, 4);
            } else {
                seed_bcast(g_opre, bo, OO, B_ * OO, j - 132, 2);
            }
        }
        gbar(sense);

        // ---- P4: Pw(36) + Pr(36) + out(32) = 104, K=256, A = tanh(hpre) ----
        for (int j = bid; j < 104; j += NB) {
            if (j < 72) {
                int head = j / 36, jj = j % 36;
                int ks = jj & 1, rest = jj >> 1;
                int row0 = (rest & 1) * 128, ct = rest >> 1;
                int col0 = ct * 64;
                int wv = PW_ - col0; if (wv > 64) wv = 64;
                const float* Wh = head ? Whr : Whw;
                float* dst = head ? g_Pr : g_Pw;
                tile_gemm2<true, 1, 1>(sh,
                    g_hpre + (size_t)row0 * H_ + ks * 256, H_,
                    Wh + (size_t)(ks * 256) * PW_ + col0, PW_, wv,
                    dst + (size_t)row0 * PSTR + col0, PSTR, 256);
            } else {
                int jj = j - 72;
                int ks = jj & 1, rest = jj >> 1;
                int row0 = (rest & 1) * 128, col0 = (rest >> 1) * 64;
                tile_gemm2<true, 0, 1>(sh,
                    g_hpre + (size_t)row0 * H_ + ks * 256, H_,
                    Wo + (size_t)(ks * 256) * OO + col0, OO, 64,
                    g_opre + (size_t)row0 * OO + col0, OO, 256);
            }
        }
        gbar(sense);

        // ---- P5: scores 128 jobs (K=256) ----
        for (int j = bid; j < 128; j += NB) {
            int z = j >> 6, jj = j & 63;
            int ks = jj & 1, rest = jj >> 1;
            int row0 = (rest & 1) * 128, n0 = (rest >> 1) * 64;
            const float* P = (z ? g_Pr : g_Pw) + (size_t)row0 * PSTR + ks * 256;
            float* Cd = (z ? g_Cr : g_Cw) + (size_t)row0 * NN + n0;
            tile_gemm2<true, 2, 1>(sh,
                P, PSTR,
                g_mem + (size_t)n0 * MM + ks * 256, MM, 64,
                Cd, NN, 256);
        }
        gbar(sense);

        // ---- P6: EA(128, K=128) + addr-dual(256) + outfin(8) = 392 ----
        for (int j = bid; j < 392; j += NB) {
            if (j < 128) {
                int ks = j & 3, rest = j >> 2;
                int row0 = (rest & 1) * 128, col0 = (rest >> 1) * 64;
                tile_gemm2<true, 0, 1>(sh,
                    g_hpre + (size_t)row0 * H_ + ks * 128, H_,
                    Wea + (size_t)(ks * 128) * (2 * MM) + col0, 2 * MM, 64,
                    g_EA + (size_t)row0 * (2 * MM) + col0, 2 * MM, 128);
            } else if (j < 384) {
                addr_dual(sh, (j - 128) * 2 + (tid >> 8));
            } else {
                int jj = j - 384;
                for (int l = tid; l < 16384; l += NT) {
                    int e = jj * 16384 + l;
                    int b = e >> 9, o = e & 511;
                    out[((size_t)b * T_ + t) * OO + o] = sigmoidf_(g_opre[e]);
                }
            }
        }
        gbar(sense);
    }
    // total barriers: 2 + 6*128 = 770 (even)
}

extern "C" void kernel_launch(void* const* d_in, const int* in_sizes, int n_in,
                              void* d_out, int out_size)
{
    (void)in_sizes; (void)n_in; (void)out_size;
    ntm_mega<<<NB, NT>>>(
        (const float*)d_in[0],  (const float*)d_in[1],  (const float*)d_in[2],
        (const float*)d_in[3],  (const float*)d_in[4],  (const float*)d_in[5],
        (const float*)d_in[6],  (const float*)d_in[7],  (const float*)d_in[8],
        (const float*)d_in[9],  (const float*)d_in[10], (const float*)d_in[11],
        (const float*)d_in[12], (const float*)d_in[13], (const float*)d_in[14],
        (const float*)d_in[15], (float*)d_out);
}

// round 9
// speedup vs baseline: 1.0548x; 1.0548x over previous
#include <cuda_runtime.h>
#include <math.h>

#define B_   256
#define T_   128
#define I_   512
#define H_   512
#define NN   1024
#define MM   512
#define OO   512
#define PW_  518          // M+6
#define PSTR 520
#define EPS  1e-8f
#define NB   144
#define NT   512

// ---------------- persistent device state ----------------
__device__ __align__(256) float g_mem[NN * MM];
__device__ __align__(256) float g_wr[B_ * NN];
__device__ __align__(256) float g_ww[B_ * NN];
__device__ __align__(256) float g_EA[B_ * 2 * MM];    // pre-act EA (direct, bea fused)
__device__ __align__(256) float g_r[B_ * MM];         // r accum (seed 0, atomics)
__device__ __align__(256) float g_hpre[B_ * H_];      // h pre-act accum (seed bh)
__device__ __align__(256) float g_Pw[B_ * PSTR];      // head pre-act (direct, bias fused)
__device__ __align__(256) float g_Pr[B_ * PSTR];
__device__ __align__(256) float g_Cw[B_ * NN];        // scores accum (seed 0)
__device__ __align__(256) float g_Cr[B_ * NN];
__device__ __align__(256) float g_memnorm[NN];
__device__ unsigned g_cnt;
__device__ volatile unsigned g_sense;

// ---------------- scalar helpers ----------------
__device__ __forceinline__ float sigmoidf_(float x) { return 1.f / (1.f + expf(-x)); }
__device__ __forceinline__ float softplusf_(float x) {
    return fmaxf(x, 0.f) + log1pf(expf(-fabsf(x)));
}
__device__ __forceinline__ float warpSum(float v) {
    #pragma unroll
    for (int o = 16; o; o >>= 1) v += __shfl_xor_sync(0xffffffffu, v, o);
    return v;
}
__device__ __forceinline__ float warpMax(float v) {
    #pragma unroll
    for (int o = 16; o; o >>= 1) v = fmaxf(v, __shfl_xor_sync(0xffffffffu, v, o));
    return v;
}

// ---------------- packed f32x2 (FFMA2) ----------------
__device__ __forceinline__ unsigned long long pack2(float a, float b) {
    unsigned long long r;
    asm("mov.b64 %0, {%1, %2};" : "=l"(r) : "f"(a), "f"(b));
    return r;
}
__device__ __forceinline__ void fma2(unsigned long long& d,
                                     unsigned long long a, unsigned long long b) {
    asm("fma.rn.f32x2 %0, %1, %2, %0;" : "+l"(d) : "l"(a), "l"(b));
}
__device__ __forceinline__ float2 unpack2(unsigned long long v) {
    float2 r;
    asm("mov.b64 {%0, %1}, %2;" : "=f"(r.x), "=f"(r.y) : "l"(v));
    return r;
}

// ---------------- grid barrier ----------------
__device__ __forceinline__ void gbar(unsigned& sense) {
    __threadfence();
    __syncthreads();
    if (threadIdx.x == 0) {
        unsigned ns = sense ^ 1u;
        if (atomicAdd(&g_cnt, 1u) == NB - 1u) {
            atomicExch(&g_cnt, 0u);
            __threadfence();
            g_sense = ns;
        } else {
            while (g_sense != ns) __nanosleep(32);
        }
        sense = ns;
        __threadfence();
    }
    __syncthreads();
}

// ---------------- 128-thread group barrier / reductions ----------------
__device__ __forceinline__ void barx128(int id) {
    asm volatile("bar.sync %0, 128;" :: "r"(id) : "memory");
}
__device__ float grpSum128(float v, float* red, int id) {
    int t = threadIdx.x & 127;
    int lane = t & 31, w = t >> 5;
    v = warpSum(v);
    if (lane == 0) red[w] = v;
    barx128(id);
    float s = red[0] + red[1] + red[2] + red[3];
    barx128(id);
    return s;
}
__device__ float grpMax128(float v, float* red, int id) {
    int t = threadIdx.x & 127;
    int lane = t & 31, w = t >> 5;
    v = warpMax(v);
    if (lane == 0) red[w] = v;
    barx128(id);
    float m = fmaxf(fmaxf(red[0], red[1]), fmaxf(red[2], red[3]));
    barx128(id);
    return m;
}

// ---------------- 128x64 GEMM tile, K-chunk 32, packed acc 4x(2x2) --------
// BMODE 0: W row-major full tile; 1: row-major + col guard; 2: transposed src.
// EPI 0: store acc(+cbias); 1: atomicAdd; 2: store sigmoid(acc+cbias).
// ATANH: tanh on A elements. All pointers pre-offset; cbias pre-offset or null.
template<bool ATANH, int BMODE, int EPI>
__device__ void tile_gemm2(
    float* sh,
    const float* __restrict__ A, int lda,
    const float* __restrict__ W, int wld, int wvalid,
    const float* __restrict__ cbias,
    float* __restrict__ C, int ldc, int K)
{
    float* As = sh;          // [2][32*132]
    float* Bs = sh + 8448;   // [2][32*68]
    const int tid = threadIdx.x;
    const int aR = tid >> 2, aK8 = (tid & 3) * 8;
    const int bK = tid >> 4, bC = (tid & 15) * 4;
    const int b2n = tid & 63, b2k = (tid >> 6) * 4;
    const int ty = tid >> 4, tx = tid & 15;
    float ar[8], bw[4];

    auto loadA = [&](int k0) {
        #pragma unroll
        for (int hh = 0; hh < 2; hh++) {
            float4 v = *(const float4*)(A + (size_t)aR * lda + k0 + aK8 + hh * 4);
            if (ATANH) {
                v.x = tanhf(v.x); v.y = tanhf(v.y);
                v.z = tanhf(v.z); v.w = tanhf(v.w);
            }
            ar[hh * 4 + 0] = v.x; ar[hh * 4 + 1] = v.y;
            ar[hh * 4 + 2] = v.z; ar[hh * 4 + 3] = v.w;
        }
    };
    auto loadB = [&](int k0) {
        if (BMODE == 0) {
            float4 v = *(const float4*)(W + (size_t)(k0 + bK) * wld + bC);
            bw[0] = v.x; bw[1] = v.y; bw[2] = v.z; bw[3] = v.w;
        } else if (BMODE == 1) {
            #pragma unroll
            for (int u = 0; u < 4; u++) {
                int c = bC + u;
                bw[u] = (c < wvalid) ? W[(size_t)(k0 + bK) * wld + c] : 0.f;
            }
        } else {
            float4 v = *(const float4*)(W + (size_t)b2n * wld + k0 + b2k);
            bw[0] = v.x; bw[1] = v.y; bw[2] = v.z; bw[3] = v.w;
        }
    };
    auto storeAB = [&](int buf) {
        float* Ab = As + buf * 4224;
        #pragma unroll
        for (int u = 0; u < 8; u++) Ab[(aK8 + u) * 132 + aR] = ar[u];
        float* Bb = Bs + buf * 2176;
        if (BMODE == 2) {
            #pragma unroll
            for (int u = 0; u < 4; u++) Bb[(b2k + u) * 68 + b2n] = bw[u];
        } else {
            *(float4*)&Bb[bK * 68 + bC] = make_float4(bw[0], bw[1], bw[2], bw[3]);
        }
    };

    unsigned long long acc2[4][2] = {};
    loadA(0); loadB(0); storeAB(0);
    __syncthreads();
    int buf = 0;
    for (int k0 = 0; k0 < K; k0 += 32) {
        bool more = (k0 + 32) < K;
        if (more) { loadA(k0 + 32); loadB(k0 + 32); }
        float* Ab = As + buf * 4224;
        float* Bb = Bs + buf * 2176;
        #pragma unroll
        for (int kk = 0; kk < 32; kk++) {
            float4 a4 = *(const float4*)&Ab[kk * 132 + ty * 4];
            ulonglong2 bp = *(const ulonglong2*)&Bb[kk * 68 + tx * 4];
            unsigned long long av;
            av = pack2(a4.x, a4.x); fma2(acc2[0][0], av, bp.x); fma2(acc2[0][1], av, bp.y);
            av = pack2(a4.y, a4.y); fma2(acc2[1][0], av, bp.x); fma2(acc2[1][1], av, bp.y);
            av = pack2(a4.z, a4.z); fma2(acc2[2][0], av, bp.x); fma2(acc2[2][1], av, bp.y);
            av = pack2(a4.w, a4.w); fma2(acc2[3][0], av, bp.x); fma2(acc2[3][1], av, bp.y);
        }
        if (more) storeAB(buf ^ 1);
        __syncthreads();
        buf ^= 1;
    }
    #pragma unroll
    for (int i = 0; i < 4; i++) {
        float* rowp = C + (size_t)(ty * 4 + i) * ldc;
        #pragma unroll
        for (int jp = 0; jp < 2; jp++) {
            float2 v = unpack2(acc2[i][jp]);
            int c0 = tx * 4 + jp * 2;
            float vv[2] = {v.x, v.y};
            #pragma unroll
            for (int u = 0; u < 2; u++) {
                int c = c0 + u;
                if (BMODE == 1 && c >= wvalid) continue;
                float val = vv[u];
                if (EPI == 1) {
                    atomicAdd(rowp + c, val);
                } else {
                    if (cbias) val += cbias[c];
                    if (EPI == 2) val = sigmoidf_(val);
                    rowp[c] = val;
                }
            }
        }
    }
}

// ---------------- memory update tile 64n x 64m (dual packed acc, K=256) ----
__device__ void tile_memupd(float* sh, int n0, int m0)
{
    float* Ws  = sh;            // [2][32][68]
    float* Es  = sh + 4352;
    float* Aas = sh + 8704;
    const int tid = threadIdx.x;
    const int wK = tid >> 4, wC = (tid & 15) * 4;
    const int ty = tid >> 5, tx = tid & 31;
    float wr_[4], ev[4], av[4];

    auto loadAll = [&](int b0) {
        float4 w = *(const float4*)(g_ww + (size_t)(b0 + wK) * NN + n0 + wC);
        wr_[0] = w.x; wr_[1] = w.y; wr_[2] = w.z; wr_[3] = w.w;
        size_t ro = (size_t)(b0 + wK) * (2 * MM);
        float4 e0 = *(const float4*)(g_EA + ro + m0 + wC);
        float4 a0 = *(const float4*)(g_EA + ro + MM + m0 + wC);
        ev[0] = sigmoidf_(e0.x); ev[1] = sigmoidf_(e0.y);
        ev[2] = sigmoidf_(e0.z); ev[3] = sigmoidf_(e0.w);
        av[0] = tanhf(a0.x); av[1] = tanhf(a0.y);
        av[2] = tanhf(a0.z); av[3] = tanhf(a0.w);
    };
    auto storeAll = [&](int buf) {
        *(float4*)&Ws [buf * 2176 + wK * 68 + wC] = make_float4(wr_[0], wr_[1], wr_[2], wr_[3]);
        *(float4*)&Es [buf * 2176 + wK * 68 + wC] = make_float4(ev[0], ev[1], ev[2], ev[3]);
        *(float4*)&Aas[buf * 2176 + wK * 68 + wC] = make_float4(av[0], av[1], av[2], av[3]);
    };

    unsigned long long ae2[4] = {}, aa2[4] = {};
    loadAll(0); storeAll(0);
    __syncthreads();
    int buf = 0;
    for (int b0 = 0; b0 < B_; b0 += 32) {
        bool more = (b0 + 32) < B_;
        if (more) loadAll(b0 + 32);
        float* Wb = Ws + buf * 2176;
        float* Eb = Es + buf * 2176;
        float* Ab = Aas + buf * 2176;
        #pragma unroll
        for (int kk = 0; kk < 32; kk++) {
            float4 w4 = *(const float4*)&Wb[kk * 68 + ty * 4];
            unsigned long long e2 = *(const unsigned long long*)&Eb[kk * 68 + tx * 2];
            unsigned long long a2 = *(const unsigned long long*)&Ab[kk * 68 + tx * 2];
            unsigned long long wv;
            wv = pack2(w4.x, w4.x); fma2(ae2[0], wv, e2); fma2(aa2[0], wv, a2);
            wv = pack2(w4.y, w4.y); fma2(ae2[1], wv, e2); fma2(aa2[1], wv, a2);
            wv = pack2(w4.z, w4.z); fma2(ae2[2], wv, e2); fma2(aa2[2], wv, a2);
            wv = pack2(w4.w, w4.w); fma2(ae2[3], wv, e2); fma2(aa2[3], wv, a2);
        }
        if (more) storeAll(buf ^ 1);
        __syncthreads();
        buf ^= 1;
    }
    const float invB = 1.f / (float)B_;
    #pragma unroll
    for (int i = 0; i < 4; i++) {
        float2 e = unpack2(ae2[i]);
        float2 a = unpack2(aa2[i]);
        size_t idx = (size_t)(n0 + ty * 4 + i) * MM + m0 + tx * 2;
        float m0v = g_mem[idx], m1v = g_mem[idx + 1];
        g_mem[idx]     = m0v * (1.f - e.x * invB) + a.x * invB;
        g_mem[idx + 1] = m1v * (1.f - e.y * invB) + a.y * invB;
    }
}

// ---------------- per-row memory norms (64 rows per job) ----------------
__device__ void norm_job(int nj) {
    const int t = threadIdx.x;
    const int row = nj * 64 + (t >> 3);
    const int p = t & 7;
    const float* rp = g_mem + (size_t)row * MM;
    float s = 0.f;
    #pragma unroll
    for (int u = 0; u < 64; u++) {
        float v = rp[p + u * 8];
        s += v * v;
    }
    s += __shfl_xor_sync(0xffffffffu, s, 1);
    s += __shfl_xor_sync(0xffffffffu, s, 2);
    s += __shfl_xor_sync(0xffffffffu, s, 4);
    if (p == 0) g_memnorm[row] = sqrtf(s);
}

// ---------------- addressing: 4 jobs/block via 128-thread groups ----------
__device__ void addr_quad(float* sh, int jbase) {
    const int g = threadIdx.x >> 7;          // group 0..3
    const int t = threadIdx.x & 127;
    const int id = 1 + g;                    // named barrier id
    float* swg  = sh + g * 1024;
    float* red  = sh + 4096 + g * 16;
    float* scal = sh + 4160 + g * 8;
    const int idx = jbase * 4 + g;           // 0..511
    const int b = idx & 255, z = idx >> 8;
    const float* P = (z ? g_Pr : g_Pw) + (size_t)b * PSTR;
    const float* C = (z ? g_Cr : g_Cw) + (size_t)b * NN;
    float* wrow = (z ? g_wr : g_ww) + (size_t)b * NN;

    barx128(id);
    float s = 0.f;
    #pragma unroll
    for (int u = 0; u < 4; u++) {
        float k = tanhf(P[t + u * 128]);
        s += k * k;
    }
    s = grpSum128(s, red, id);
    if (t == 0) {
        scal[6] = sqrtf(s) + EPS;
        float p0 = P[MM], p1 = P[MM + 1], p2 = P[MM + 2];
        float p3 = P[MM + 3], p4 = P[MM + 4], p5 = P[MM + 5];
        scal[0] = softplusf_(p0);
        scal[1] = sigmoidf_(p1);
        float m = fmaxf(p2, fmaxf(p3, p4));
        float e0 = expf(p2 - m), e1 = expf(p3 - m), e2 = expf(p4 - m);
        float ss = e0 + e1 + e2;
        scal[2] = e0 / ss; scal[3] = e1 / ss; scal[4] = e2 / ss;
        scal[5] = 1.f + softplusf_(p5);
    }
    barx128(id);
    float beta = scal[0], gg = scal[1], s0 = scal[2], s1 = scal[3], s2 = scal[4];
    float gamma = scal[5], knorm = scal[6];

    float v[8];
    float mx = -3.4e38f;
    #pragma unroll
    for (int u = 0; u < 8; u++) {
        int n = t + u * 128;
        float sc = beta * C[n] / (knorm * (g_memnorm[n] + EPS));
        v[u] = sc;
        mx = fmaxf(mx, sc);
    }
    mx = grpMax128(mx, red, id);
    float se = 0.f;
    #pragma unroll
    for (int u = 0; u < 8; u++) {
        v[u] = expf(v[u] - mx);
        se += v[u];
    }
    se = grpSum128(se, red, id);
    float inv = 1.f / se;
    #pragma unroll
    for (int u = 0; u < 8; u++) {
        int n = t + u * 128;
        swg[n] = gg * v[u] * inv + (1.f - gg) * wrow[n];
    }
    barx128(id);
    float S = 0.f;
    #pragma unroll
    for (int u = 0; u < 8; u++) {
        int n = t + u * 128;
        float wt = s1 * swg[n] + s0 * swg[(n + 1) & (NN - 1)] + s2 * swg[(n - 1) & (NN - 1)];
        v[u] = powf(wt, gamma);
        S += v[u];
    }
    S = grpSum128(S, red, id);
    float invS = 1.f / (S + EPS);
    #pragma unroll
    for (int u = 0; u < 8; u++)
        wrow[t + u * 128] = v[u] * invS;
}

// ---------------- seed helpers ----------------
__device__ void seed_bcast(float* dst, const float* src, int width, int total,
                           int part, int parts) {
    int per = total / parts;
    int base = part * per;
    for (int i = threadIdx.x; i < per; i += NT) {
        int idx = base + i;
        dst[idx] = src[idx % width];
    }
}
__device__ void seed_zero(float* dst, int total, int part, int parts) {
    int per4 = total / (4 * parts);
    float4* d = (float4*)dst + part * per4;
    float4 z = make_float4(0.f, 0.f, 0.f, 0.f);
    for (int i = threadIdx.x; i < per4; i += NT) d[i] = z;
}

// ---------------- the megakernel ----------------
__global__ void __launch_bounds__(NT, 1) ntm_mega(
    const float* __restrict__ x,
    const float* __restrict__ mem0, const float* __restrict__ wr0,
    const float* __restrict__ ww0, const float* __restrict__ h0,
    const float* __restrict__ Wx, const float* __restrict__ Wr,
    const float* __restrict__ bh,
    const float* __restrict__ Whr, const float* __restrict__ bhr,
    const float* __restrict__ Whw, const float* __restrict__ bhw,
    const float* __restrict__ Wea, const float* __restrict__ bea,
    const float* __restrict__ Wo, const float* __restrict__ bo,
    float* __restrict__ out)
{
    __shared__ __align__(16) float sh[13120];
    unsigned sense = 0;
    const int bid = blockIdx.x;
    const int tid = threadIdx.x;
    const int gthread = bid * NT + tid;

    // INIT: copy state; EA(0) = h0 @ Wea + bea (direct, 32 jobs K=512)
    for (int i = gthread; i < NN * MM; i += NB * NT) g_mem[i] = mem0[i];
    for (int i = gthread; i < B_ * NN; i += NB * NT) {
        g_wr[i] = wr0[i];
        g_ww[i] = ww0[i];
    }
    __syncthreads();
    for (int j = bid; j < 32; j += NB) {
        int rt = j & 1, ct = j >> 1;
        int row0 = rt * 128, col0 = ct * 64;
        tile_gemm2<false, 0, 0>(sh,
            h0 + (size_t)row0 * H_, H_,
            Wea + col0, 2 * MM, 64, bea + col0,
            g_EA + (size_t)row0 * (2 * MM) + col0, 2 * MM, 512);
    }
    gbar(sense);                                             // 1

    for (int t = 0; t < T_; t++) {
        // ---- P1: memupd(128) + seed r(2) + seed hpre(2) = 132 ----
        for (int j = bid; j < 132; j += NB) {
            if (j < 128) {
                tile_memupd(sh, (j >> 3) * 64, (j & 7) * 64);
            } else if (j < 130) {
                seed_zero(g_r, B_ * MM, j - 128, 2);
            } else {
                seed_bcast(g_hpre, bh, H_, B_ * H_, j - 130, 2);
            }
        }
        gbar(sense);

        // ---- P2: r(64, K=256) + hx(32, K=256) + norms(16) + seedC(8) = 120 --
        for (int j = bid; j < 120; j += NB) {
            if (j < 64) {
                int ks = j & 3, rest = j >> 2;
                int row0 = (rest & 1) * 128, col0 = (rest >> 1) * 64;
                tile_gemm2<false, 0, 1>(sh,
                    g_wr + (size_t)row0 * NN + ks * 256, NN,
                    g_mem + (size_t)(ks * 256) * MM + col0, MM, 64, nullptr,
                    g_r + (size_t)row0 * MM + col0, MM, 256);
            } else if (j < 96) {
                int jj = j - 64;
                int ks = jj & 1, rest = jj >> 1;
                int row0 = (rest & 1) * 128, col0 = (rest >> 1) * 64;
                tile_gemm2<false, 0, 1>(sh,
                    x + (size_t)row0 * (T_ * I_) + (size_t)t * I_ + ks * 256, T_ * I_,
                    Wx + (size_t)(ks * 256) * H_ + col0, H_, 64, nullptr,
                    g_hpre + (size_t)row0 * H_ + col0, H_, 256);
            } else if (j < 112) {
                norm_job(j - 96);
            } else {
                int jj = j - 112;
                if (jj < 4) seed_zero(g_Cw, B_ * NN, jj, 4);
                else        seed_zero(g_Cr, B_ * NN, jj - 4, 4);
            }
        }
        gbar(sense);

        // ---- P3: hr(128, K=64 ksplit8) = 128 ----
        for (int j = bid; j < 128; j += NB) {
            int ks = j & 7, rest = j >> 3;
            int row0 = (rest & 1) * 128, col0 = (rest >> 1) * 64;
            tile_gemm2<false, 0, 1>(sh,
                g_r + (size_t)row0 * MM + ks * 64, MM,
                Wr + (size_t)(ks * 64) * H_ + col0, H_, 64, nullptr,
                g_hpre + (size_t)row0 * H_ + col0, H_, 64);
        }
        gbar(sense);

        // ---- P4: Pw(18) + Pr(18) + EA(32) + out(16) = 84 jobs, all K=512 ----
        for (int j = bid; j < 84; j += NB) {
            if (j < 36) {
                int head = j / 18, jj = j % 18;
                int rt = jj / 9, ct = jj % 9;
                int row0 = rt * 128, col0 = ct * 64;
                int wv = PW_ - col0; if (wv > 64) wv = 64;
                const float* Wh = head ? Whr : Whw;
                const float* bp = head ? bhr : bhw;
                float* dst = head ? g_Pr : g_Pw;
                tile_gemm2<true, 1, 0>(sh,
                    g_hpre + (size_t)row0 * H_, H_,
                    Wh + col0, PW_, wv, bp + col0,
                    dst + (size_t)row0 * PSTR + col0, PSTR, 512);
            } else if (j < 68) {
                int jj = j - 36;
                int rt = jj & 1, ct = jj >> 1;
                int row0 = rt * 128, col0 = ct * 64;
                tile_gemm2<true, 0, 0>(sh,
                    g_hpre + (size_t)row0 * H_, H_,
                    Wea + col0, 2 * MM, 64, bea + col0,
                    g_EA + (size_t)row0 * (2 * MM) + col0, 2 * MM, 512);
            } else {
                int jj = j - 68;
                int rt = jj & 1, ct = jj >> 1;
                int row0 = rt * 128, col0 = ct * 64;
                tile_gemm2<true, 0, 2>(sh,
                    g_hpre + (size_t)row0 * H_, H_,
                    Wo + col0, OO, 64, bo + col0,
                    out + (size_t)row0 * (T_ * OO) + (size_t)t * OO + col0,
                    T_ * OO, 512);
            }
        }
        gbar(sense);

        // ---- P5: scores 128 jobs (K=256) ----
        for (int j = bid; j < 128; j += NB) {
            int z = j >> 6, jj = j & 63;
            int ks = jj & 1, rest = jj >> 1;
            int row0 = (rest & 1) * 128, n0 = (rest >> 1) * 64;
            const float* P = (z ? g_Pr : g_Pw) + (size_t)row0 * PSTR + ks * 256;
            float* Cd = (z ? g_Cr : g_Cw) + (size_t)row0 * NN + n0;
            tile_gemm2<true, 2, 1>(sh,
                P, PSTR,
                g_mem + (size_t)n0 * MM + ks * 256, MM, 64, nullptr,
                Cd, NN, 256);
        }
        gbar(sense);

        // ---- P6: addressing, 128 quad jobs (4 per block) ----
        for (int j = bid; j < 128; j += NB)
            addr_quad(sh, j);
        gbar(sense);
    }
    gbar(sense);   // parity: 1 + 6*128 + 1 = 770 (even)
}

extern "C" void kernel_launch(void* const* d_in, const int* in_sizes, int n_in,
                              void* d_out, int out_size)
{
    (void)in_sizes; (void)n_in; (void)out_size;
    ntm_mega<<<NB, NT>>>(
        (const float*)d_in[0],  (const float*)d_in[1],  (const float*)d_in[2],
        (const float*)d_in[3],  (const float*)d_in[4],  (const float*)d_in[5],
        (const float*)d_in[6],  (const float*)d_in[7],  (const float*)d_in[8],
        (const float*)d_in[9],  (const float*)d_in[10], (const float*)d_in[11],
        (const float*)d_in[12], (const float*)d_in[13], (const float*)d_in[14],
        (const float*)d_in[15], (float*)d_out);
}